// round 12
// baseline (speedup 1.0000x reference)
#include <cuda_runtime.h>
#include <cuda_fp16.h>
#include <cstdint>

// MeanShift step, N=M=8192, D=32, fp32, via fp16 HMMA (m16n8k16), flash-style.
// out[i,:] = sum_j k_ij y_j / sum_j k_ij, k_ij = exp(-||x_i-y_j||^2/128).
// exp(-x_i^2/128) cancels in the ratio -> k' = exp2((y^2 - 2 x.y) * F).
// GEMM1 fp16-acc (2 chained k-steps; dk/k ~ 1e-4). GEMM2 fp32-acc with
// fp16(y); residual restored in finalize by global rank-1 mean correction.
// TI=64 / 128-thread CTAs @ occ 8 -> 1024 CTAs: per-SM load max/avg = 1.01.

#define N_PTS 8192
#define DIM   32
#define TI    64
#define TJ    128
#define NWARP 4
#define JSPLIT 8
#define JCHUNK (N_PTS / JSPLIT)   // 1024
#define NTILES (JCHUNK / TJ)      // 8
#define YROW   20                 // half2 per j-row (80B: ldmatrix conflict-free)

__device__ float g_acc_part[JSPLIT * N_PTS * DIM];
__device__ float g_den_part[JSPLIT * N_PTS];
__device__ float g_sylo_part[64 * DIM];

__device__ __forceinline__ float ex2f(float t) {
    float r; asm("ex2.approx.f32 %0, %1;" : "=f"(r) : "f"(t)); return r;
}
__device__ __forceinline__ uint32_t packh2(float lo, float hi) {
    __half2 h = __floats2half2_rn(lo, hi);
    return *reinterpret_cast<uint32_t*>(&h);
}
// fp16 accumulator (GEMM1)
__device__ __forceinline__ void mma_f16acc(uint32_t* c, const uint32_t* a,
                                           uint32_t b0, uint32_t b1) {
    asm volatile(
        "mma.sync.aligned.m16n8k16.row.col.f16.f16.f16.f16 "
        "{%0,%1}, {%2,%3,%4,%5}, {%6,%7}, {%0,%1};"
        : "+r"(c[0]), "+r"(c[1])
        : "r"(a[0]), "r"(a[1]), "r"(a[2]), "r"(a[3]), "r"(b0), "r"(b1));
}
// fp32 accumulator (GEMM2)
__device__ __forceinline__ void mma_f16(float* c, const uint32_t* a, uint32_t b0, uint32_t b1) {
    asm volatile(
        "mma.sync.aligned.m16n8k16.row.col.f32.f16.f16.f32 "
        "{%0,%1,%2,%3}, {%4,%5,%6,%7}, {%8,%9}, {%0,%1,%2,%3};"
        : "+f"(c[0]), "+f"(c[1]), "+f"(c[2]), "+f"(c[3])
        : "r"(a[0]), "r"(a[1]), "r"(a[2]), "r"(a[3]), "r"(b0), "r"(b1));
}
__device__ __forceinline__ void ldsm_x4(uint32_t* r, uint32_t addr) {
    asm volatile("ldmatrix.sync.aligned.m8n8.x4.shared.b16 {%0,%1,%2,%3}, [%4];"
                 : "=r"(r[0]), "=r"(r[1]), "=r"(r[2]), "=r"(r[3]) : "r"(addr));
}
__device__ __forceinline__ void ldsm_x4t(uint32_t* r, uint32_t addr) {
    asm volatile("ldmatrix.sync.aligned.m8n8.x4.trans.shared.b16 {%0,%1,%2,%3}, [%4];"
                 : "=r"(r[0]), "=r"(r[1]), "=r"(r[2]), "=r"(r[3]) : "r"(addr));
}

// ---- tiny kernel: per-128j-block residual column sums (64 CTAs) ----
__global__ __launch_bounds__(256)
void sylo_part_k(const float* __restrict__ ref) {
    __shared__ float part[8][DIM];
    const int t = threadIdx.x, d = t & 31, g = t >> 5;
    const float* yg = ref + ((size_t)blockIdx.x * 128 + g * 16) * DIM + d;
    float a = 0.f;
    #pragma unroll
    for (int j = 0; j < 16; j++) {
        float v = yg[j * DIM];
        a += v - __half2float(__float2half_rn(v));
    }
    part[g][d] = a;
    __syncthreads();
    if (t < DIM) {
        float s = 0.f;
        #pragma unroll
        for (int gg = 0; gg < 8; gg++) s += part[gg][t];
        g_sylo_part[blockIdx.x * DIM + t] = s;
    }
}

__global__ __launch_bounds__(128, 8)
void meanshift_h(const float* __restrict__ pts, const float* __restrict__ ref) {
    __shared__ __half2 ysh_hi[2][TJ * YROW];   // 20480 B
    __shared__ float   y2F[2][TJ];

    const int tid  = threadIdx.x;
    const int wi   = tid >> 5;      // 0..3
    const int lane = tid & 31;
    const int r    = lane >> 2;
    const int c    = lane & 3;
    const int i0   = blockIdx.x * TI + wi * 16;
    const int j0   = blockIdx.y * JCHUNK;

    const float F   = -1.4426950408889634f / 128.0f;   // -log2(e)/(2*8^2)
    const float m2F = -2.0f * F;

    const int m8 = lane >> 3;
    const int l7 = lane & 7;
    const uint32_t offG1 = (uint32_t)((((m8 >> 1) & 1) * 8 + l7) * 80 + (m8 & 1) * 16);
    const uint32_t offG2 = (uint32_t)(((m8 & 1) * 8 + l7) * 80 + (m8 >> 1) * 16);

    // X A-fragments (fp16), hoisted
    uint32_t xa[2][4];
    {
        const float2* x0 = reinterpret_cast<const float2*>(pts + (size_t)(i0 + r) * DIM);
        const float2* x1 = reinterpret_cast<const float2*>(pts + (size_t)(i0 + r + 8) * DIM);
        #pragma unroll
        for (int kk = 0; kk < 2; kk++) {
            float2 v;
            v = x0[kk * 8 + c];     xa[kk][0] = packh2(v.x, v.y);
            v = x1[kk * 8 + c];     xa[kk][1] = packh2(v.x, v.y);
            v = x0[kk * 8 + c + 4]; xa[kk][2] = packh2(v.x, v.y);
            v = x1[kk * 8 + c + 4]; xa[kk][3] = packh2(v.x, v.y);
        }
    }

    float d2[4][4];
    #pragma unroll
    for (int nc = 0; nc < 4; nc++)
        #pragma unroll
        for (int q = 0; q < 4; q++) d2[nc][q] = 0.f;
    float den0 = 0.f, den1 = 0.f;

    auto stage = [&](int tt, int b) {
        // 128 threads: one j-row each
        const int j = j0 + tt * TJ + tid;
        const float4* yp = reinterpret_cast<const float4*>(ref + (size_t)j * DIM);
        float y2 = 0.f;
        #pragma unroll
        for (int q = 0; q < 8; q++) {
            float4 v = yp[q];
            y2 += v.x * v.x + v.y * v.y + v.z * v.z + v.w * v.w;
            ysh_hi[b][tid * YROW + 2 * q]     = __floats2half2_rn(v.x, v.y);
            ysh_hi[b][tid * YROW + 2 * q + 1] = __floats2half2_rn(v.z, v.w);
        }
        y2F[b][tid] = y2 * F;
    };

    stage(0, 0);
    __syncthreads();

    for (int t = 0; t < NTILES; t++) {
        const int b = t & 1;
        if (t + 1 < NTILES) stage(t + 1, b ^ 1);

        const uint32_t ybh = (uint32_t)__cvta_generic_to_shared(&ysh_hi[b][0]);

        #pragma unroll 2
        for (int g = 0; g < 8; g++) {
            const uint32_t gbase = (uint32_t)(g * 16 * 80);

            // GEMM1: S[16 x 16] = X . Y^T, fp16 accumulate
            uint32_t sA[2] = {0u, 0u};
            uint32_t sB[2] = {0u, 0u};
            #pragma unroll
            for (int kk = 0; kk < 2; kk++) {
                uint32_t bf[4];
                ldsm_x4(bf, ybh + gbase + offG1 + (uint32_t)(kk * 32));
                mma_f16acc(sA, xa[kk], bf[0], bf[1]);
                mma_f16acc(sB, xa[kk], bf[2], bf[3]);
            }

            float2 sA0 = __half22float2(*reinterpret_cast<__half2*>(&sA[0]));
            float2 sA1 = __half22float2(*reinterpret_cast<__half2*>(&sA[1]));
            float2 sB0 = __half22float2(*reinterpret_cast<__half2*>(&sB[0]));
            float2 sB1 = __half22float2(*reinterpret_cast<__half2*>(&sB[1]));

            float2 yA = *reinterpret_cast<const float2*>(&y2F[b][g * 16 + 2 * c]);
            float2 yB = *reinterpret_cast<const float2*>(&y2F[b][g * 16 + 8 + 2 * c]);
            float kA0 = ex2f(fmaf(sA0.x, m2F, yA.x));
            float kA1 = ex2f(fmaf(sA0.y, m2F, yA.y));
            float kA2 = ex2f(fmaf(sA1.x, m2F, yA.x));
            float kA3 = ex2f(fmaf(sA1.y, m2F, yA.y));
            float kB0 = ex2f(fmaf(sB0.x, m2F, yB.x));
            float kB1 = ex2f(fmaf(sB0.y, m2F, yB.y));
            float kB2 = ex2f(fmaf(sB1.x, m2F, yB.x));
            float kB3 = ex2f(fmaf(sB1.y, m2F, yB.y));

            uint32_t ka[4];
            ka[0] = packh2(kA0, kA1);
            ka[1] = packh2(kA2, kA3);
            ka[2] = packh2(kB0, kB1);
            ka[3] = packh2(kB2, kB3);

            den0 += (kA0 + kA1) + (kB0 + kB1);
            den1 += (kA2 + kA3) + (kB2 + kB3);

            // GEMM2: D2[16 x 32] += K . Y_hi (fp32 acc, reuse distance 4)
            uint32_t bh0[4], bh1[4];
            ldsm_x4t(bh0, ybh + gbase + offG2);
            ldsm_x4t(bh1, ybh + gbase + offG2 + 32u);
            mma_f16(d2[0], ka, bh0[0], bh0[1]);
            mma_f16(d2[1], ka, bh0[2], bh0[3]);
            mma_f16(d2[2], ka, bh1[0], bh1[1]);
            mma_f16(d2[3], ka, bh1[2], bh1[3]);
        }
        __syncthreads();
    }

    // writeback partials (deterministic)
    {
        den0 += __shfl_xor_sync(0xffffffffu, den0, 1);
        den0 += __shfl_xor_sync(0xffffffffu, den0, 2);
        den1 += __shfl_xor_sync(0xffffffffu, den1, 1);
        den1 += __shfl_xor_sync(0xffffffffu, den1, 2);

        float* gw = g_acc_part + ((size_t)blockIdx.y * N_PTS + i0) * DIM;
        #pragma unroll
        for (int nc = 0; nc < 4; nc++) {
            *reinterpret_cast<float2*>(&gw[(size_t)r * DIM       + nc * 8 + 2 * c]) =
                make_float2(d2[nc][0], d2[nc][1]);
            *reinterpret_cast<float2*>(&gw[(size_t)(r + 8) * DIM + nc * 8 + 2 * c]) =
                make_float2(d2[nc][2], d2[nc][3]);
        }
        if (c == 0) {
            g_den_part[blockIdx.y * N_PTS + i0 + r]     = den0;
            g_den_part[blockIdx.y * N_PTS + i0 + r + 8] = den1;
        }
    }
}

// finalize: block-local sylo reduction + partial sums + correction + divide
__global__ __launch_bounds__(256)
void meanshift_finalize(float* __restrict__ out) {
    __shared__ float sy[DIM];

    // reduce the 64 sylo partials once per block (64*32 = 2048 loads / 256 thr)
    {
        const int d = threadIdx.x & 31, s8 = threadIdx.x >> 5;   // 8 stripes
        float a = 0.f;
        #pragma unroll
        for (int b = 0; b < 8; b++) a += g_sylo_part[(s8 * 8 + b) * DIM + d];
        // cross-stripe reduce via shmem-free warp trick: 8 partial owners per d
        __shared__ float syp[8][DIM];
        syp[s8][d] = a;
        __syncthreads();
        if (threadIdx.x < DIM) {
            float t = 0.f;
            #pragma unroll
            for (int s = 0; s < 8; s++) t += syp[s][threadIdx.x];
            sy[threadIdx.x] = t * (1.0f / (float)N_PTS);
        }
        __syncthreads();
    }

    const int e4 = blockIdx.x * blockDim.x + threadIdx.x;   // over N*D/4
    const int i  = e4 >> 3;
    const int db = (e4 & 7) * 4;

    float den = 0.f;
    #pragma unroll
    for (int s = 0; s < JSPLIT; s++) den += g_den_part[s * N_PTS + i];

    float4 acc = make_float4(0.f, 0.f, 0.f, 0.f);
    #pragma unroll
    for (int s = 0; s < JSPLIT; s++) {
        float4 v = *reinterpret_cast<const float4*>(
            &g_acc_part[(size_t)s * N_PTS * DIM + (size_t)i * DIM + db]);
        acc.x += v.x; acc.y += v.y; acc.z += v.z; acc.w += v.w;
    }

    float4 s4 = *reinterpret_cast<const float4*>(&sy[db]);
    float inv = __fdividef(1.0f, den);
    float4 o;
    o.x = fmaf(den, s4.x, acc.x) * inv;
    o.y = fmaf(den, s4.y, acc.y) * inv;
    o.z = fmaf(den, s4.z, acc.z) * inv;
    o.w = fmaf(den, s4.w, acc.w) * inv;
    *reinterpret_cast<float4*>(&out[e4 * 4]) = o;
}

extern "C" void kernel_launch(void* const* d_in, const int* in_sizes, int n_in,
                              void* d_out, int out_size) {
    const float* pts = (const float*)d_in[0];
    const float* ref = (const float*)d_in[1];
    float* out = (float*)d_out;

    sylo_part_k<<<64, 256>>>(ref);
    dim3 grid(N_PTS / TI, JSPLIT);   // 128 x 8 = 1024 CTAs @ occ 8
    meanshift_h<<<grid, 128>>>(pts, ref);
    meanshift_finalize<<<(N_PTS * DIM / 4) / 256, 256>>>(out);
}

// round 13
// speedup vs baseline: 1.2181x; 1.2181x over previous
#include <cuda_runtime.h>
#include <cuda_fp16.h>
#include <cstdint>

// MeanShift step, N=M=8192, D=32, fp32, via fp16 HMMA (m16n8k16), flash-style.
// out[i,:] = sum_j k_ij y_j / sum_j k_ij, k_ij = exp(-||x_i-y_j||^2/128).
// exp(-x_i^2/128) cancels in the ratio -> k' = exp2((y^2 - 2 x.y) * F).
// GEMM2 uses fp16(y); quantization residual restored in FINALIZE by a global
// rank-1 mean-field correction. JSPLIT=16 -> 1024 half-length CTAs for
// fine-grained load balance (staging total unchanged vs JSPLIT=8).

#define N_PTS 8192
#define DIM   32
#define TI    128
#define TJ    128
#define JSPLIT 16
#define JCHUNK (N_PTS / JSPLIT)   // 512
#define NTILES (JCHUNK / TJ)      // 4
#define YROW   20                 // half2 per j-row (80B: ldmatrix conflict-free)

__device__ float g_acc_part[JSPLIT * N_PTS * DIM];   // 16 MB
__device__ float g_den_part[JSPLIT * N_PTS];
__device__ float g_sylo_part[64 * DIM];

__device__ __forceinline__ float ex2f(float t) {
    float r; asm("ex2.approx.f32 %0, %1;" : "=f"(r) : "f"(t)); return r;
}
__device__ __forceinline__ uint32_t packh2(float lo, float hi) {
    __half2 h = __floats2half2_rn(lo, hi);
    return *reinterpret_cast<uint32_t*>(&h);
}
__device__ __forceinline__ void mma_f16(float* c, const uint32_t* a, uint32_t b0, uint32_t b1) {
    asm volatile(
        "mma.sync.aligned.m16n8k16.row.col.f32.f16.f16.f32 "
        "{%0,%1,%2,%3}, {%4,%5,%6,%7}, {%8,%9}, {%0,%1,%2,%3};"
        : "+f"(c[0]), "+f"(c[1]), "+f"(c[2]), "+f"(c[3])
        : "r"(a[0]), "r"(a[1]), "r"(a[2]), "r"(a[3]), "r"(b0), "r"(b1));
}
__device__ __forceinline__ void ldsm_x4(uint32_t* r, uint32_t addr) {
    asm volatile("ldmatrix.sync.aligned.m8n8.x4.shared.b16 {%0,%1,%2,%3}, [%4];"
                 : "=r"(r[0]), "=r"(r[1]), "=r"(r[2]), "=r"(r[3]) : "r"(addr));
}
__device__ __forceinline__ void ldsm_x4t(uint32_t* r, uint32_t addr) {
    asm volatile("ldmatrix.sync.aligned.m8n8.x4.trans.shared.b16 {%0,%1,%2,%3}, [%4];"
                 : "=r"(r[0]), "=r"(r[1]), "=r"(r[2]), "=r"(r[3]) : "r"(addr));
}

// ---- tiny kernel: per-128j-block residual column sums (64 CTAs) ----
__global__ __launch_bounds__(256)
void sylo_part_k(const float* __restrict__ ref) {
    __shared__ float part[8][DIM];
    const int t = threadIdx.x, d = t & 31, g = t >> 5;
    const float* yg = ref + ((size_t)blockIdx.x * 128 + g * 16) * DIM + d;
    float a = 0.f;
    #pragma unroll
    for (int j = 0; j < 16; j++) {
        float v = yg[j * DIM];
        a += v - __half2float(__float2half_rn(v));
    }
    part[g][d] = a;
    __syncthreads();
    if (t < DIM) {
        float s = 0.f;
        #pragma unroll
        for (int gg = 0; gg < 8; gg++) s += part[gg][t];
        g_sylo_part[blockIdx.x * DIM + t] = s;
    }
}

__global__ __launch_bounds__(256, 4)
void meanshift_h(const float* __restrict__ pts, const float* __restrict__ ref) {
    __shared__ __half2 ysh_hi[2][TJ * YROW];   // 20480 B
    __shared__ float   y2F[2][TJ];

    const int tid  = threadIdx.x;
    const int wi   = tid >> 5;
    const int lane = tid & 31;
    const int r    = lane >> 2;
    const int c    = lane & 3;
    const int i0   = blockIdx.x * TI + wi * 16;
    const int j0   = blockIdx.y * JCHUNK;

    const float F   = -1.4426950408889634f / 128.0f;   // -log2(e)/(2*8^2)
    const float m2F = -2.0f * F;

    const int m8 = lane >> 3;
    const int l7 = lane & 7;
    const uint32_t offG1 = (uint32_t)((((m8 >> 1) & 1) * 8 + l7) * 80 + (m8 & 1) * 16);
    const uint32_t offG2 = (uint32_t)(((m8 & 1) * 8 + l7) * 80 + (m8 >> 1) * 16);

    // X A-fragments (fp16), hoisted
    uint32_t xa[2][4];
    {
        const float2* x0 = reinterpret_cast<const float2*>(pts + (size_t)(i0 + r) * DIM);
        const float2* x1 = reinterpret_cast<const float2*>(pts + (size_t)(i0 + r + 8) * DIM);
        #pragma unroll
        for (int kk = 0; kk < 2; kk++) {
            float2 v;
            v = x0[kk * 8 + c];     xa[kk][0] = packh2(v.x, v.y);
            v = x1[kk * 8 + c];     xa[kk][1] = packh2(v.x, v.y);
            v = x0[kk * 8 + c + 4]; xa[kk][2] = packh2(v.x, v.y);
            v = x1[kk * 8 + c + 4]; xa[kk][3] = packh2(v.x, v.y);
        }
    }

    float d2[4][4];
    #pragma unroll
    for (int nc = 0; nc < 4; nc++)
        #pragma unroll
        for (int q = 0; q < 4; q++) d2[nc][q] = 0.f;
    float den0 = 0.f, den1 = 0.f;

    auto stage = [&](int tt, int b) {
        if (tid < TJ) {
            const int j = j0 + tt * TJ + tid;
            const float4* yp = reinterpret_cast<const float4*>(ref + (size_t)j * DIM);
            float y2 = 0.f;
            #pragma unroll
            for (int q = 0; q < 8; q++) {
                float4 v = yp[q];
                y2 += v.x * v.x + v.y * v.y + v.z * v.z + v.w * v.w;
                ysh_hi[b][tid * YROW + 2 * q]     = __floats2half2_rn(v.x, v.y);
                ysh_hi[b][tid * YROW + 2 * q + 1] = __floats2half2_rn(v.z, v.w);
            }
            y2F[b][tid] = y2 * F;
        }
    };

    stage(0, 0);
    __syncthreads();

    for (int t = 0; t < NTILES; t++) {
        const int b = t & 1;
        if (t + 1 < NTILES) stage(t + 1, b ^ 1);

        const uint32_t ybh = (uint32_t)__cvta_generic_to_shared(&ysh_hi[b][0]);

        #pragma unroll 2
        for (int g = 0; g < 8; g++) {
            const uint32_t gbase = (uint32_t)(g * 16 * 80);

            // GEMM1: S[16 x 16] = X . Y^T (fp32 accumulate)
            float sA[4] = {0.f, 0.f, 0.f, 0.f};
            float sB[4] = {0.f, 0.f, 0.f, 0.f};
            #pragma unroll
            for (int kk = 0; kk < 2; kk++) {
                uint32_t bf[4];
                ldsm_x4(bf, ybh + gbase + offG1 + (uint32_t)(kk * 32));
                mma_f16(sA, xa[kk], bf[0], bf[1]);
                mma_f16(sB, xa[kk], bf[2], bf[3]);
            }

            // exp -> k (fp16); C-frag layout == A-frag layout
            float2 yA = *reinterpret_cast<const float2*>(&y2F[b][g * 16 + 2 * c]);
            float2 yB = *reinterpret_cast<const float2*>(&y2F[b][g * 16 + 8 + 2 * c]);
            float kA0 = ex2f(fmaf(sA[0], m2F, yA.x));
            float kA1 = ex2f(fmaf(sA[1], m2F, yA.y));
            float kA2 = ex2f(fmaf(sA[2], m2F, yA.x));
            float kA3 = ex2f(fmaf(sA[3], m2F, yA.y));
            float kB0 = ex2f(fmaf(sB[0], m2F, yB.x));
            float kB1 = ex2f(fmaf(sB[1], m2F, yB.y));
            float kB2 = ex2f(fmaf(sB[2], m2F, yB.x));
            float kB3 = ex2f(fmaf(sB[3], m2F, yB.y));

            uint32_t ka[4];
            ka[0] = packh2(kA0, kA1);
            ka[1] = packh2(kA2, kA3);
            ka[2] = packh2(kB0, kB1);
            ka[3] = packh2(kB2, kB3);

            den0 += (kA0 + kA1) + (kB0 + kB1);
            den1 += (kA2 + kA3) + (kB2 + kB3);

            // GEMM2: D2[16 x 32] += K . Y_hi (fp32 acc, reuse distance 4)
            uint32_t bh0[4], bh1[4];
            ldsm_x4t(bh0, ybh + gbase + offG2);
            ldsm_x4t(bh1, ybh + gbase + offG2 + 32u);
            mma_f16(d2[0], ka, bh0[0], bh0[1]);
            mma_f16(d2[1], ka, bh0[2], bh0[3]);
            mma_f16(d2[2], ka, bh1[0], bh1[1]);
            mma_f16(d2[3], ka, bh1[2], bh1[3]);
        }
        __syncthreads();
    }

    // writeback partials (deterministic)
    {
        den0 += __shfl_xor_sync(0xffffffffu, den0, 1);
        den0 += __shfl_xor_sync(0xffffffffu, den0, 2);
        den1 += __shfl_xor_sync(0xffffffffu, den1, 1);
        den1 += __shfl_xor_sync(0xffffffffu, den1, 2);

        float* gw = g_acc_part + ((size_t)blockIdx.y * N_PTS + i0) * DIM;
        #pragma unroll
        for (int nc = 0; nc < 4; nc++) {
            *reinterpret_cast<float2*>(&gw[(size_t)r * DIM       + nc * 8 + 2 * c]) =
                make_float2(d2[nc][0], d2[nc][1]);
            *reinterpret_cast<float2*>(&gw[(size_t)(r + 8) * DIM + nc * 8 + 2 * c]) =
                make_float2(d2[nc][2], d2[nc][3]);
        }
        if (c == 0) {
            g_den_part[blockIdx.y * N_PTS + i0 + r]     = den0;
            g_den_part[blockIdx.y * N_PTS + i0 + r + 8] = den1;
        }
    }
}

// finalize: block-local sylo reduction + partial sums + correction + divide
__global__ __launch_bounds__(256)
void meanshift_finalize(float* __restrict__ out) {
    __shared__ float sy[DIM];
    __shared__ float syp[8][DIM];
    {
        const int d = threadIdx.x & 31, s8 = threadIdx.x >> 5;
        float a = 0.f;
        #pragma unroll
        for (int b = 0; b < 8; b++) a += g_sylo_part[(s8 * 8 + b) * DIM + d];
        syp[s8][d] = a;
        __syncthreads();
        if (threadIdx.x < DIM) {
            float t = 0.f;
            #pragma unroll
            for (int s = 0; s < 8; s++) t += syp[s][threadIdx.x];
            sy[threadIdx.x] = t * (1.0f / (float)N_PTS);
        }
        __syncthreads();
    }

    const int e4 = blockIdx.x * blockDim.x + threadIdx.x;   // over N*D/4
    const int i  = e4 >> 3;
    const int db = (e4 & 7) * 4;

    float den = 0.f;
    #pragma unroll
    for (int s = 0; s < JSPLIT; s++) den += g_den_part[s * N_PTS + i];

    float4 acc = make_float4(0.f, 0.f, 0.f, 0.f);
    #pragma unroll
    for (int s = 0; s < JSPLIT; s++) {
        float4 v = *reinterpret_cast<const float4*>(
            &g_acc_part[(size_t)s * N_PTS * DIM + (size_t)i * DIM + db]);
        acc.x += v.x; acc.y += v.y; acc.z += v.z; acc.w += v.w;
    }

    float4 s4 = *reinterpret_cast<const float4*>(&sy[db]);
    float inv = __fdividef(1.0f, den);
    float4 o;
    o.x = fmaf(den, s4.x, acc.x) * inv;
    o.y = fmaf(den, s4.y, acc.y) * inv;
    o.z = fmaf(den, s4.z, acc.z) * inv;
    o.w = fmaf(den, s4.w, acc.w) * inv;
    *reinterpret_cast<float4*>(&out[e4 * 4]) = o;
}

extern "C" void kernel_launch(void* const* d_in, const int* in_sizes, int n_in,
                              void* d_out, int out_size) {
    const float* pts = (const float*)d_in[0];
    const float* ref = (const float*)d_in[1];
    float* out = (float*)d_out;

    sylo_part_k<<<64, 256>>>(ref);
    dim3 grid(N_PTS / TI, JSPLIT);   // 64 x 16 = 1024 half-length CTAs @ occ 4
    meanshift_h<<<grid, 256>>>(pts, ref);
    meanshift_finalize<<<(N_PTS * DIM / 4) / 256, 256>>>(out);
}

// round 14
// speedup vs baseline: 1.2638x; 1.0375x over previous
#include <cuda_runtime.h>
#include <cuda_fp16.h>
#include <cstdint>

// MeanShift step, N=M=8192, D=32, fp32, via fp16 HMMA (m16n8k16), flash-style.
// out[i,:] = sum_j k_ij y_j / sum_j k_ij, k_ij = exp(-||x_i-y_j||^2/128).
// exp(-x_i^2/128) cancels in the ratio -> k' = exp2((y^2 - 2 x.y) * F).
// GEMM2 uses fp16(y); quantization residual restored in FINALIZE by a global
// rank-1 mean-field correction. JSPLIT=16 -> 1024 half-length CTAs.
// The residual column sums (sylo) are folded into the main kernel: the 16
// CTAs with blockIdx.x==0 each sum their own j-chunk (no extra launch).

#define N_PTS 8192
#define DIM   32
#define TI    128
#define TJ    128
#define JSPLIT 16
#define JCHUNK (N_PTS / JSPLIT)   // 512
#define NTILES (JCHUNK / TJ)      // 4
#define YROW   20                 // half2 per j-row (80B: ldmatrix conflict-free)

__device__ float g_acc_part[JSPLIT * N_PTS * DIM];   // 16 MB
__device__ float g_den_part[JSPLIT * N_PTS];
__device__ float g_sylo_part[JSPLIT * DIM];

__device__ __forceinline__ float ex2f(float t) {
    float r; asm("ex2.approx.f32 %0, %1;" : "=f"(r) : "f"(t)); return r;
}
__device__ __forceinline__ uint32_t packh2(float lo, float hi) {
    __half2 h = __floats2half2_rn(lo, hi);
    return *reinterpret_cast<uint32_t*>(&h);
}
__device__ __forceinline__ void mma_f16(float* c, const uint32_t* a, uint32_t b0, uint32_t b1) {
    asm volatile(
        "mma.sync.aligned.m16n8k16.row.col.f32.f16.f16.f32 "
        "{%0,%1,%2,%3}, {%4,%5,%6,%7}, {%8,%9}, {%0,%1,%2,%3};"
        : "+f"(c[0]), "+f"(c[1]), "+f"(c[2]), "+f"(c[3])
        : "r"(a[0]), "r"(a[1]), "r"(a[2]), "r"(a[3]), "r"(b0), "r"(b1));
}
__device__ __forceinline__ void ldsm_x4(uint32_t* r, uint32_t addr) {
    asm volatile("ldmatrix.sync.aligned.m8n8.x4.shared.b16 {%0,%1,%2,%3}, [%4];"
                 : "=r"(r[0]), "=r"(r[1]), "=r"(r[2]), "=r"(r[3]) : "r"(addr));
}
__device__ __forceinline__ void ldsm_x4t(uint32_t* r, uint32_t addr) {
    asm volatile("ldmatrix.sync.aligned.m8n8.x4.trans.shared.b16 {%0,%1,%2,%3}, [%4];"
                 : "=r"(r[0]), "=r"(r[1]), "=r"(r[2]), "=r"(r[3]) : "r"(addr));
}

__global__ __launch_bounds__(256, 4)
void meanshift_h(const float* __restrict__ pts, const float* __restrict__ ref) {
    __shared__ __half2 ysh_hi[2][TJ * YROW];   // 20480 B
    __shared__ float   y2F[2][TJ];
    __shared__ float   syp2[8][DIM];           // sylo stripe reduction

    const int tid  = threadIdx.x;
    const int wi   = tid >> 5;
    const int lane = tid & 31;
    const int r    = lane >> 2;
    const int c    = lane & 3;
    const int i0   = blockIdx.x * TI + wi * 16;
    const int j0   = blockIdx.y * JCHUNK;

    const float F   = -1.4426950408889634f / 128.0f;   // -log2(e)/(2*8^2)
    const float m2F = -2.0f * F;

    const int m8 = lane >> 3;
    const int l7 = lane & 7;
    const uint32_t offG1 = (uint32_t)((((m8 >> 1) & 1) * 8 + l7) * 80 + (m8 & 1) * 16);
    const uint32_t offG2 = (uint32_t)(((m8 & 1) * 8 + l7) * 80 + (m8 >> 1) * 16);

    // X A-fragments (fp16), hoisted
    uint32_t xa[2][4];
    {
        const float2* x0 = reinterpret_cast<const float2*>(pts + (size_t)(i0 + r) * DIM);
        const float2* x1 = reinterpret_cast<const float2*>(pts + (size_t)(i0 + r + 8) * DIM);
        #pragma unroll
        for (int kk = 0; kk < 2; kk++) {
            float2 v;
            v = x0[kk * 8 + c];     xa[kk][0] = packh2(v.x, v.y);
            v = x1[kk * 8 + c];     xa[kk][1] = packh2(v.x, v.y);
            v = x0[kk * 8 + c + 4]; xa[kk][2] = packh2(v.x, v.y);
            v = x1[kk * 8 + c + 4]; xa[kk][3] = packh2(v.x, v.y);
        }
    }

    float d2[4][4];
    #pragma unroll
    for (int nc = 0; nc < 4; nc++)
        #pragma unroll
        for (int q = 0; q < 4; q++) d2[nc][q] = 0.f;
    float den0 = 0.f, den1 = 0.f;

    auto stage = [&](int tt, int b) {
        if (tid < TJ) {
            const int j = j0 + tt * TJ + tid;
            const float4* yp = reinterpret_cast<const float4*>(ref + (size_t)j * DIM);
            float y2 = 0.f;
            #pragma unroll
            for (int q = 0; q < 8; q++) {
                float4 v = yp[q];
                y2 += v.x * v.x + v.y * v.y + v.z * v.z + v.w * v.w;
                ysh_hi[b][tid * YROW + 2 * q]     = __floats2half2_rn(v.x, v.y);
                ysh_hi[b][tid * YROW + 2 * q + 1] = __floats2half2_rn(v.z, v.w);
            }
            y2F[b][tid] = y2 * F;
        }
    };

    stage(0, 0);
    __syncthreads();

    for (int t = 0; t < NTILES; t++) {
        const int b = t & 1;
        if (t + 1 < NTILES) stage(t + 1, b ^ 1);

        const uint32_t ybh = (uint32_t)__cvta_generic_to_shared(&ysh_hi[b][0]);

        #pragma unroll 2
        for (int g = 0; g < 8; g++) {
            const uint32_t gbase = (uint32_t)(g * 16 * 80);

            // GEMM1: S[16 x 16] = X . Y^T (fp32 accumulate)
            float sA[4] = {0.f, 0.f, 0.f, 0.f};
            float sB[4] = {0.f, 0.f, 0.f, 0.f};
            #pragma unroll
            for (int kk = 0; kk < 2; kk++) {
                uint32_t bf[4];
                ldsm_x4(bf, ybh + gbase + offG1 + (uint32_t)(kk * 32));
                mma_f16(sA, xa[kk], bf[0], bf[1]);
                mma_f16(sB, xa[kk], bf[2], bf[3]);
            }

            // exp -> k (fp16); C-frag layout == A-frag layout
            float2 yA = *reinterpret_cast<const float2*>(&y2F[b][g * 16 + 2 * c]);
            float2 yB = *reinterpret_cast<const float2*>(&y2F[b][g * 16 + 8 + 2 * c]);
            float kA0 = ex2f(fmaf(sA[0], m2F, yA.x));
            float kA1 = ex2f(fmaf(sA[1], m2F, yA.y));
            float kA2 = ex2f(fmaf(sA[2], m2F, yA.x));
            float kA3 = ex2f(fmaf(sA[3], m2F, yA.y));
            float kB0 = ex2f(fmaf(sB[0], m2F, yB.x));
            float kB1 = ex2f(fmaf(sB[1], m2F, yB.y));
            float kB2 = ex2f(fmaf(sB[2], m2F, yB.x));
            float kB3 = ex2f(fmaf(sB[3], m2F, yB.y));

            uint32_t ka[4];
            ka[0] = packh2(kA0, kA1);
            ka[1] = packh2(kA2, kA3);
            ka[2] = packh2(kB0, kB1);
            ka[3] = packh2(kB2, kB3);

            den0 += (kA0 + kA1) + (kB0 + kB1);
            den1 += (kA2 + kA3) + (kB2 + kB3);

            // GEMM2: D2[16 x 32] += K . Y_hi (fp32 acc, reuse distance 4)
            uint32_t bh0[4], bh1[4];
            ldsm_x4t(bh0, ybh + gbase + offG2);
            ldsm_x4t(bh1, ybh + gbase + offG2 + 32u);
            mma_f16(d2[0], ka, bh0[0], bh0[1]);
            mma_f16(d2[1], ka, bh0[2], bh0[3]);
            mma_f16(d2[2], ka, bh1[0], bh1[1]);
            mma_f16(d2[3], ka, bh1[2], bh1[3]);
        }
        __syncthreads();
    }

    // writeback partials (deterministic)
    {
        den0 += __shfl_xor_sync(0xffffffffu, den0, 1);
        den0 += __shfl_xor_sync(0xffffffffu, den0, 2);
        den1 += __shfl_xor_sync(0xffffffffu, den1, 1);
        den1 += __shfl_xor_sync(0xffffffffu, den1, 2);

        float* gw = g_acc_part + ((size_t)blockIdx.y * N_PTS + i0) * DIM;
        #pragma unroll
        for (int nc = 0; nc < 4; nc++) {
            *reinterpret_cast<float2*>(&gw[(size_t)r * DIM       + nc * 8 + 2 * c]) =
                make_float2(d2[nc][0], d2[nc][1]);
            *reinterpret_cast<float2*>(&gw[(size_t)(r + 8) * DIM + nc * 8 + 2 * c]) =
                make_float2(d2[nc][2], d2[nc][3]);
        }
        if (c == 0) {
            g_den_part[blockIdx.y * N_PTS + i0 + r]     = den0;
            g_den_part[blockIdx.y * N_PTS + i0 + r + 8] = den1;
        }
    }

    // ---- sylo for this j-chunk: only the blockIdx.x==0 i-block does it ----
    if (blockIdx.x == 0) {
        const int d = tid & 31, s8 = tid >> 5;   // 8 stripes x 64 rows
        const float* yg = ref + (size_t)(j0 + s8 * 64) * DIM + d;
        float a = 0.f;
        #pragma unroll 8
        for (int j = 0; j < 64; j++) {
            float v = yg[j * DIM];
            a += v - __half2float(__float2half_rn(v));
        }
        syp2[s8][d] = a;
        __syncthreads();
        if (tid < DIM) {
            float s = 0.f;
            #pragma unroll
            for (int ss = 0; ss < 8; ss++) s += syp2[ss][tid];
            g_sylo_part[blockIdx.y * DIM + tid] = s;
        }
    }
}

// finalize: sylo reduction (16 partials) + partial sums + correction + divide
__global__ __launch_bounds__(256)
void meanshift_finalize(float* __restrict__ out) {
    __shared__ float sy[DIM];
    __shared__ float syp[8][DIM];
    {
        const int d = threadIdx.x & 31, s8 = threadIdx.x >> 5;   // 8 stripes x 2
        float a = g_sylo_part[(s8 * 2) * DIM + d] + g_sylo_part[(s8 * 2 + 1) * DIM + d];
        syp[s8][d] = a;
        __syncthreads();
        if (threadIdx.x < DIM) {
            float t = 0.f;
            #pragma unroll
            for (int s = 0; s < 8; s++) t += syp[s][threadIdx.x];
            sy[threadIdx.x] = t * (1.0f / (float)N_PTS);
        }
        __syncthreads();
    }

    const int e4 = blockIdx.x * blockDim.x + threadIdx.x;   // over N*D/4
    const int i  = e4 >> 3;
    const int db = (e4 & 7) * 4;

    float den = 0.f;
    #pragma unroll
    for (int s = 0; s < JSPLIT; s++) den += g_den_part[s * N_PTS + i];

    float4 acc = make_float4(0.f, 0.f, 0.f, 0.f);
    #pragma unroll
    for (int s = 0; s < JSPLIT; s++) {
        float4 v = *reinterpret_cast<const float4*>(
            &g_acc_part[(size_t)s * N_PTS * DIM + (size_t)i * DIM + db]);
        acc.x += v.x; acc.y += v.y; acc.z += v.z; acc.w += v.w;
    }

    float4 s4 = *reinterpret_cast<const float4*>(&sy[db]);
    float inv = __fdividef(1.0f, den);
    float4 o;
    o.x = fmaf(den, s4.x, acc.x) * inv;
    o.y = fmaf(den, s4.y, acc.y) * inv;
    o.z = fmaf(den, s4.z, acc.z) * inv;
    o.w = fmaf(den, s4.w, acc.w) * inv;
    *reinterpret_cast<float4*>(&out[e4 * 4]) = o;
}

extern "C" void kernel_launch(void* const* d_in, const int* in_sizes, int n_in,
                              void* d_out, int out_size) {
    const float* pts = (const float*)d_in[0];
    const float* ref = (const float*)d_in[1];
    float* out = (float*)d_out;

    dim3 grid(N_PTS / TI, JSPLIT);   // 64 x 16 = 1024 half-length CTAs @ occ 4
    meanshift_h<<<grid, 256>>>(pts, ref);
    meanshift_finalize<<<(N_PTS * DIM / 4) / 256, 256>>>(out);
}